// round 14
// baseline (speedup 1.0000x reference)
#include <cuda_runtime.h>
#include <cstdint>

// ---------------------------------------------------------------------------
// SDPQuantizer: global min/max -> int8 quantize -> split high/low nibble ->
// per-8-group top-4 mask on low nibble -> dequantize.
// x: (8, 4096, 2048) fp32 = 67,108,864 elements = 256 MB. Output fp32.
//
// R13 discovery: 64B lane stride made every warp-LDG.128 touch 16 lines
// (L1tex wavefront-bound); 32B-stride pair layout halves that and lifted
// quant to 6.15 TB/s. This round applies the same pair layout to the minmax
// read pass (replacing the R12 TMA workaround).
//
// Kernel 1 (minmax): thread t loads float4 pairs (2t,2t+1), (512+2t,512+2t+1)
//   of a 1024-float4 chunk (streaming), REDUX reduce, one atomic per block.
// Kernel 2 (quant, R13-proven): same pair layout, rank-4 selection network,
//   reciprocal-multiply with rare exact-division tie rescue. 78.3us.
// ---------------------------------------------------------------------------

__device__ unsigned int g_min_enc = 0x80000000u;  // enc(0.0f)
__device__ unsigned int g_max_enc = 0x80000000u;

__device__ __forceinline__ unsigned int enc_f(float f) {
    unsigned int u = __float_as_uint(f);
    return (u & 0x80000000u) ? ~u : (u | 0x80000000u);
}
__device__ __forceinline__ float dec_f(unsigned int u) {
    return (u & 0x80000000u) ? __uint_as_float(u & 0x7FFFFFFFu)
                             : __uint_as_float(~u);
}
__device__ __forceinline__ float v4min(float4 v) {
    return fminf(fminf(v.x, v.y), fminf(v.z, v.w));
}
__device__ __forceinline__ float v4max(float4 v) {
    return fmaxf(fmaxf(v.x, v.y), fmaxf(v.z, v.w));
}

// One thread = 16 elements in pair layout (32B lane stride -> 8 lines per
// warp-LDG.128). Exact coverage: gridDim.x == n4/1024.
__global__ void sdp_minmax_kernel(const float4* __restrict__ x) {
    const size_t chunk = (size_t)blockIdx.x * 1024;   // float4 units
    const int t = threadIdx.x;
    const size_t i0 = chunk + 2 * t;
    const size_t i1 = chunk + 512 + 2 * t;

    float4 v0 = __ldcs(&x[i0]);
    float4 v1 = __ldcs(&x[i0 + 1]);
    float4 v2 = __ldcs(&x[i1]);
    float4 v3 = __ldcs(&x[i1 + 1]);

    float lmin = fminf(fminf(v4min(v0), v4min(v1)), fminf(v4min(v2), v4min(v3)));
    float lmax = fmaxf(fmaxf(v4max(v0), v4max(v1)), fmaxf(v4max(v2), v4max(v3)));
    lmin = fminf(lmin, 0.0f);
    lmax = fmaxf(lmax, 0.0f);

    unsigned int emin = __reduce_min_sync(0xFFFFFFFFu, enc_f(lmin));
    unsigned int emax = __reduce_max_sync(0xFFFFFFFFu, enc_f(lmax));

    __shared__ unsigned int smin[8], smax[8];
    const int lane = t & 31;
    const int warp = t >> 5;
    if (lane == 0) { smin[warp] = emin; smax[warp] = emax; }
    __syncthreads();
    if (t < 8) {
        emin = __reduce_min_sync(0xFFu, smin[t]);
        emax = __reduce_max_sync(0xFFu, smax[t]);
        if (t == 0) {
            atomicMin(&g_min_enc, emin);
            atomicMax(&g_max_enc, emax);
        }
    }
}

// compare-exchange: u becomes max, v becomes min
#define SDP_CE(u, v) { float _hi = fmaxf(u, v), _lo = fminf(u, v); u = _hi; v = _lo; }

__device__ __forceinline__ void sdp_process_group(
    float4 va, float4 vb, float scale, float inv_scale,
    float4& oa, float4& ob)
{
    float xv[8]  = {va.x, va.y, va.z, va.w, vb.x, vb.y, vb.z, vb.w};
    float q[8];
    float mag[8];

    #pragma unroll
    for (int i = 0; i < 8; i++) {
        // Reciprocal-multiply fast path; can only flip round-half-to-even on
        // a near-.5 tie: detect and redo with exact IEEE division (rare).
        float y = xv[i] * inv_scale;
        float r = rintf(y);
        if (fabsf(fabsf(y - r) - 0.5f) < 1e-3f) {
            r = rintf(__fdiv_rn(xv[i], scale));
        }
        r = fminf(fmaxf(r, -128.0f), 127.0f);
        q[i]   = r;
        mag[i] = fabsf(r);   // integer-valued, 0..128
    }

    // 4th-largest of 8 via two sorted-4 runs + merge rank selection.
    float a0 = mag[0], a1 = mag[1], a2 = mag[2], a3 = mag[3];
    float b0 = mag[4], b1 = mag[5], b2 = mag[6], b3 = mag[7];
    SDP_CE(a0, a1); SDP_CE(a2, a3); SDP_CE(a0, a2); SDP_CE(a1, a3); SDP_CE(a1, a2);
    SDP_CE(b0, b1); SDP_CE(b2, b3); SDP_CE(b0, b2); SDP_CE(b1, b3); SDP_CE(b1, b2);
    float thr = fmaxf(fmaxf(a3, b3),
                      fmaxf(fminf(a0, b2), fmaxf(fminf(a1, b1), fminf(a2, b0))));

    #pragma unroll
    for (int i = 0; i < 8; i++) {
        const float tr16 = floorf(mag[i] * 0.0625f) * 16.0f;
        const float val  = (mag[i] >= thr) ? mag[i] : tr16;
        const float x_sdp = scale * copysignf(val, q[i]);
        xv[i] = xv[i] + (x_sdp - xv[i]);   // replicate reference rounding
    }

    oa = make_float4(xv[0], xv[1], xv[2], xv[3]);
    ob = make_float4(xv[4], xv[5], xv[6], xv[7]);
}

// One thread = two groups, pair layout (R13-proven: 78.3us, 6.15 TB/s).
__global__ void sdp_quant_kernel(const float4* __restrict__ x,
                                 float4* __restrict__ out) {
    const float r_min = dec_f(g_min_enc);
    const float r_max = dec_f(g_max_enc);
    const float scale = fmaxf(__fdiv_rn(r_max - r_min, 255.0f), 1e-8f);
    const float inv_scale = __frcp_rn(scale);

    const size_t chunk = (size_t)blockIdx.x * 1024;   // float4 units
    const int t = threadIdx.x;
    const size_t i0 = chunk + 2 * t;          // first group (pair)
    const size_t i1 = chunk + 512 + 2 * t;    // second group (pair)

    float4 v0 = __ldcs(&x[i0]);
    float4 v1 = __ldcs(&x[i0 + 1]);
    float4 v2 = __ldcs(&x[i1]);
    float4 v3 = __ldcs(&x[i1 + 1]);

    float4 o0, o1, o2, o3;
    sdp_process_group(v0, v1, scale, inv_scale, o0, o1);
    sdp_process_group(v2, v3, scale, inv_scale, o2, o3);

    __stcs(&out[i0],     o0);
    __stcs(&out[i0 + 1], o1);
    __stcs(&out[i1],     o2);
    __stcs(&out[i1 + 1], o3);
}

extern "C" void kernel_launch(void* const* d_in, const int* in_sizes, int n_in,
                              void* d_out, int out_size) {
    const float* x = (const float*)d_in[0];
    float* out = (float*)d_out;
    const int n = in_sizes[0];          // 67,108,864 floats = 256 MB
    const int n4 = n >> 2;              // 16,777,216 float4

    const int threads = 256;
    const int blocks = n4 / 1024;       // 16384 chunks of 1024 float4

    sdp_minmax_kernel<<<blocks, threads>>>((const float4*)x);
    sdp_quant_kernel<<<blocks, threads>>>((const float4*)x, (float4*)out);
}

// round 15
// speedup vs baseline: 1.0133x; 1.0133x over previous
#include <cuda_runtime.h>
#include <cstdint>

// ---------------------------------------------------------------------------
// SDPQuantizer: global min/max -> int8 quantize -> split high/low nibble ->
// per-8-group top-4 mask on low nibble -> dequantize.
// x: (8, 4096, 2048) fp32 = 67,108,864 elements = 256 MB. Output fp32.
//
// Kernel 1 (minmax): TMA read engine, 2-stage pipeline. Each of 8192 CTAs
//   issues TWO 16KB cp.async.bulk copies up-front (2x in-flight bytes),
//   reduces buffer 0 while buffer 1 lands. REDUX + one atomic per block.
// Kernel 2 (quant, R13-proven, 77.9us @ 6.17 TB/s): pair layout (32B lane
//   stride halves L1tex wavefronts), rank-4 selection network,
//   reciprocal-multiply with rare exact-division tie rescue.
// ---------------------------------------------------------------------------

__device__ unsigned int g_min_enc = 0x80000000u;  // enc(0.0f)
__device__ unsigned int g_max_enc = 0x80000000u;

__device__ __forceinline__ unsigned int enc_f(float f) {
    unsigned int u = __float_as_uint(f);
    return (u & 0x80000000u) ? ~u : (u | 0x80000000u);
}
__device__ __forceinline__ float dec_f(unsigned int u) {
    return (u & 0x80000000u) ? __uint_as_float(u & 0x7FFFFFFFu)
                             : __uint_as_float(~u);
}
__device__ __forceinline__ float v4min(float4 v) {
    return fminf(fminf(v.x, v.y), fminf(v.z, v.w));
}
__device__ __forceinline__ float v4max(float4 v) {
    return fmaxf(fmaxf(v.x, v.y), fmaxf(v.z, v.w));
}
__device__ __forceinline__ unsigned int smem_u32(const void* p) {
    unsigned int a;
    asm("{ .reg .u64 t; cvta.to.shared.u64 t, %1; cvt.u32.u64 %0, t; }"
        : "=r"(a) : "l"(p));
    return a;
}
__device__ __forceinline__ void mbar_wait0(unsigned int mbar_a) {
    asm volatile(
        "{\n\t"
        ".reg .pred P;\n\t"
        "WAIT_%=:\n\t"
        "mbarrier.try_wait.parity.acquire.cta.shared::cta.b64 P, [%0], 0, 0x989680;\n\t"
        "@P bra DONE_%=;\n\t"
        "bra WAIT_%=;\n\t"
        "DONE_%=:\n\t"
        "}"
        :: "r"(mbar_a) : "memory");
}

#define SDP_STAGE_BYTES 16384           // 16KB per stage = 1024 float4
#define SDP_STAGE_V4    1024
#define SDP_CHUNK_BYTES 32768           // 32KB per CTA (2 stages)

// One CTA = one 32KB span, copied as two pipelined 16KB TMA stages.
__global__ void __launch_bounds__(256)
sdp_minmax_kernel(const float* __restrict__ x) {
    __shared__ alignas(128) float4 buf[2][SDP_STAGE_V4];
    __shared__ alignas(8) unsigned long long mbar[2];

    const int t = threadIdx.x;
    const unsigned int mbar0 = smem_u32(&mbar[0]);
    const unsigned int mbar1 = smem_u32(&mbar[1]);

    if (t == 0) {
        asm volatile("mbarrier.init.shared.b64 [%0], 1;" :: "r"(mbar0) : "memory");
        asm volatile("mbarrier.init.shared.b64 [%0], 1;" :: "r"(mbar1) : "memory");
        asm volatile("fence.proxy.async.shared::cta;" ::: "memory");
    }
    __syncthreads();

    if (t == 0) {
        const char* src = (const char*)x + (size_t)blockIdx.x * SDP_CHUNK_BYTES;
        const unsigned int b0 = smem_u32(buf[0]);
        const unsigned int b1 = smem_u32(buf[1]);
        asm volatile("mbarrier.arrive.expect_tx.shared.b64 _, [%0], %1;"
                     :: "r"(mbar0), "r"((unsigned)SDP_STAGE_BYTES) : "memory");
        asm volatile(
            "cp.async.bulk.shared::cta.global.mbarrier::complete_tx::bytes "
            "[%0], [%1], %2, [%3];"
            :: "r"(b0), "l"(src), "r"((unsigned)SDP_STAGE_BYTES), "r"(mbar0)
            : "memory");
        asm volatile("mbarrier.arrive.expect_tx.shared.b64 _, [%0], %1;"
                     :: "r"(mbar1), "r"((unsigned)SDP_STAGE_BYTES) : "memory");
        asm volatile(
            "cp.async.bulk.shared::cta.global.mbarrier::complete_tx::bytes "
            "[%0], [%1], %2, [%3];"
            :: "r"(b1), "l"(src + SDP_STAGE_BYTES),
               "r"((unsigned)SDP_STAGE_BYTES), "r"(mbar1)
            : "memory");
    }

    float lmin = 0.0f, lmax = 0.0f;

    // Stage 0: wait + reduce (4 float4/thread, stride-1 conflict-free).
    mbar_wait0(mbar0);
    #pragma unroll
    for (int k = 0; k < 4; k++) {
        float4 v = buf[0][t + k * 256];
        lmin = fminf(lmin, v4min(v));
        lmax = fmaxf(lmax, v4max(v));
    }
    // Stage 1: wait + reduce (overlapped with stage-0 reduce in flight).
    mbar_wait0(mbar1);
    #pragma unroll
    for (int k = 0; k < 4; k++) {
        float4 v = buf[1][t + k * 256];
        lmin = fminf(lmin, v4min(v));
        lmax = fmaxf(lmax, v4max(v));
    }

    unsigned int emin = __reduce_min_sync(0xFFFFFFFFu, enc_f(lmin));
    unsigned int emax = __reduce_max_sync(0xFFFFFFFFu, enc_f(lmax));

    __shared__ unsigned int smin[8], smax[8];
    const int lane = t & 31;
    const int warp = t >> 5;
    if (lane == 0) { smin[warp] = emin; smax[warp] = emax; }
    __syncthreads();
    if (t < 8) {
        emin = __reduce_min_sync(0xFFu, smin[t]);
        emax = __reduce_max_sync(0xFFu, smax[t]);
        if (t == 0) {
            atomicMin(&g_min_enc, emin);
            atomicMax(&g_max_enc, emax);
        }
    }
}

// compare-exchange: u becomes max, v becomes min
#define SDP_CE(u, v) { float _hi = fmaxf(u, v), _lo = fminf(u, v); u = _hi; v = _lo; }

__device__ __forceinline__ void sdp_process_group(
    float4 va, float4 vb, float scale, float inv_scale,
    float4& oa, float4& ob)
{
    float xv[8]  = {va.x, va.y, va.z, va.w, vb.x, vb.y, vb.z, vb.w};
    float q[8];
    float mag[8];

    #pragma unroll
    for (int i = 0; i < 8; i++) {
        // Reciprocal-multiply fast path; can only flip round-half-to-even on
        // a near-.5 tie: detect and redo with exact IEEE division (rare).
        float y = xv[i] * inv_scale;
        float r = rintf(y);
        if (fabsf(fabsf(y - r) - 0.5f) < 1e-3f) {
            r = rintf(__fdiv_rn(xv[i], scale));
        }
        r = fminf(fmaxf(r, -128.0f), 127.0f);
        q[i]   = r;
        mag[i] = fabsf(r);   // integer-valued, 0..128
    }

    // 4th-largest of 8 via two sorted-4 runs + merge rank selection.
    float a0 = mag[0], a1 = mag[1], a2 = mag[2], a3 = mag[3];
    float b0 = mag[4], b1 = mag[5], b2 = mag[6], b3 = mag[7];
    SDP_CE(a0, a1); SDP_CE(a2, a3); SDP_CE(a0, a2); SDP_CE(a1, a3); SDP_CE(a1, a2);
    SDP_CE(b0, b1); SDP_CE(b2, b3); SDP_CE(b0, b2); SDP_CE(b1, b3); SDP_CE(b1, b2);
    float thr = fmaxf(fmaxf(a3, b3),
                      fmaxf(fminf(a0, b2), fmaxf(fminf(a1, b1), fminf(a2, b0))));

    #pragma unroll
    for (int i = 0; i < 8; i++) {
        const float tr16 = floorf(mag[i] * 0.0625f) * 16.0f;
        const float val  = (mag[i] >= thr) ? mag[i] : tr16;
        const float x_sdp = scale * copysignf(val, q[i]);
        xv[i] = xv[i] + (x_sdp - xv[i]);   // replicate reference rounding
    }

    oa = make_float4(xv[0], xv[1], xv[2], xv[3]);
    ob = make_float4(xv[4], xv[5], xv[6], xv[7]);
}

// One thread = two groups, pair layout (R13-proven: 77.9us, 6.17 TB/s).
__global__ void sdp_quant_kernel(const float4* __restrict__ x,
                                 float4* __restrict__ out) {
    const float r_min = dec_f(g_min_enc);
    const float r_max = dec_f(g_max_enc);
    const float scale = fmaxf(__fdiv_rn(r_max - r_min, 255.0f), 1e-8f);
    const float inv_scale = __frcp_rn(scale);

    const size_t chunk = (size_t)blockIdx.x * 1024;   // float4 units
    const int t = threadIdx.x;
    const size_t i0 = chunk + 2 * t;          // first group (pair)
    const size_t i1 = chunk + 512 + 2 * t;    // second group (pair)

    float4 v0 = __ldcs(&x[i0]);
    float4 v1 = __ldcs(&x[i0 + 1]);
    float4 v2 = __ldcs(&x[i1]);
    float4 v3 = __ldcs(&x[i1 + 1]);

    float4 o0, o1, o2, o3;
    sdp_process_group(v0, v1, scale, inv_scale, o0, o1);
    sdp_process_group(v2, v3, scale, inv_scale, o2, o3);

    __stcs(&out[i0],     o0);
    __stcs(&out[i0 + 1], o1);
    __stcs(&out[i1],     o2);
    __stcs(&out[i1 + 1], o3);
}

extern "C" void kernel_launch(void* const* d_in, const int* in_sizes, int n_in,
                              void* d_out, int out_size) {
    const float* x = (const float*)d_in[0];
    float* out = (float*)d_out;
    const int n = in_sizes[0];          // 67,108,864 floats = 256 MB
    const int n4 = n >> 2;              // 16,777,216 float4

    const int threads = 256;

    const int mm_blocks = (int)((size_t)n * 4 / SDP_CHUNK_BYTES);  // 8192
    sdp_minmax_kernel<<<mm_blocks, threads>>>(x);

    const int q_blocks = n4 / 1024;     // 16384 chunks of 1024 float4
    sdp_quant_kernel<<<q_blocks, threads>>>((const float4*)x, (float4*)out);
}

// round 16
// speedup vs baseline: 1.0173x; 1.0039x over previous
#include <cuda_runtime.h>
#include <cstdint>

// ---------------------------------------------------------------------------
// SDPQuantizer: global min/max -> int8 quantize -> split high/low nibble ->
// per-8-group top-4 mask on low nibble -> dequantize.
// x: (8, 4096, 2048) fp32 = 67,108,864 elements = 256 MB. Output fp32.
//
// Kernel 1 (minmax, R13-proven 46.1us): single 32KB TMA bulk-copy per CTA
//   into SMEM + reduce. Forward order -> the TAIL ~126MB of x is L2-resident
//   at kernel end (TMA reads allocate via LTS).
// Kernel 2 (quant, R13 pair layout, now DRAM-bound): REVERSED chunk order so
//   its first waves consume the L2-hot tail of x. R4/R7 reuse attempts were
//   confounded: quant was L1-wavefront-bound then, so L2 hits couldn't pay.
// ---------------------------------------------------------------------------

__device__ unsigned int g_min_enc = 0x80000000u;  // enc(0.0f)
__device__ unsigned int g_max_enc = 0x80000000u;

__device__ __forceinline__ unsigned int enc_f(float f) {
    unsigned int u = __float_as_uint(f);
    return (u & 0x80000000u) ? ~u : (u | 0x80000000u);
}
__device__ __forceinline__ float dec_f(unsigned int u) {
    return (u & 0x80000000u) ? __uint_as_float(u & 0x7FFFFFFFu)
                             : __uint_as_float(~u);
}
__device__ __forceinline__ float v4min(float4 v) {
    return fminf(fminf(v.x, v.y), fminf(v.z, v.w));
}
__device__ __forceinline__ float v4max(float4 v) {
    return fmaxf(fmaxf(v.x, v.y), fmaxf(v.z, v.w));
}
__device__ __forceinline__ unsigned int smem_u32(const void* p) {
    unsigned int a;
    asm("{ .reg .u64 t; cvta.to.shared.u64 t, %1; cvt.u32.u64 %0, t; }"
        : "=r"(a) : "l"(p));
    return a;
}

#define SDP_CHUNK_BYTES 32768           // 32KB per CTA = 2048 float4
#define SDP_CHUNK_V4    2048

// One CTA = one 32KB chunk via cp.async.bulk into SMEM, then reduce.
__global__ void __launch_bounds__(256)
sdp_minmax_kernel(const float* __restrict__ x) {
    __shared__ alignas(128) float4 buf[SDP_CHUNK_V4];
    __shared__ alignas(8) unsigned long long mbar;

    const int t = threadIdx.x;
    const unsigned int mbar_a = smem_u32(&mbar);
    const unsigned int buf_a  = smem_u32(buf);

    if (t == 0) {
        asm volatile("mbarrier.init.shared.b64 [%0], 1;" :: "r"(mbar_a) : "memory");
        asm volatile("fence.proxy.async.shared::cta;" ::: "memory");
    }
    __syncthreads();

    if (t == 0) {
        asm volatile("mbarrier.arrive.expect_tx.shared.b64 _, [%0], %1;"
                     :: "r"(mbar_a), "r"((unsigned)SDP_CHUNK_BYTES) : "memory");
        const char* src = (const char*)x + (size_t)blockIdx.x * SDP_CHUNK_BYTES;
        asm volatile(
            "cp.async.bulk.shared::cta.global.mbarrier::complete_tx::bytes "
            "[%0], [%1], %2, [%3];"
            :: "r"(buf_a), "l"(src), "r"((unsigned)SDP_CHUNK_BYTES), "r"(mbar_a)
            : "memory");
    }

    // All threads wait (parity 0; barrier freshly initialized -> replay-safe).
    asm volatile(
        "{\n\t"
        ".reg .pred P;\n\t"
        "WAIT_%=:\n\t"
        "mbarrier.try_wait.parity.acquire.cta.shared::cta.b64 P, [%0], 0, 0x989680;\n\t"
        "@P bra DONE_%=;\n\t"
        "bra WAIT_%=;\n\t"
        "DONE_%=:\n\t"
        "}"
        :: "r"(mbar_a) : "memory");

    // Reduce 8 float4 per thread, stride-1 across threads (conflict-free).
    float lmin = 0.0f, lmax = 0.0f;
    #pragma unroll
    for (int k = 0; k < 8; k++) {
        float4 v = buf[t + k * 256];
        lmin = fminf(lmin, v4min(v));
        lmax = fmaxf(lmax, v4max(v));
    }

    unsigned int emin = __reduce_min_sync(0xFFFFFFFFu, enc_f(lmin));
    unsigned int emax = __reduce_max_sync(0xFFFFFFFFu, enc_f(lmax));

    __shared__ unsigned int smin[8], smax[8];
    const int lane = t & 31;
    const int warp = t >> 5;
    if (lane == 0) { smin[warp] = emin; smax[warp] = emax; }
    __syncthreads();
    if (t < 8) {
        emin = __reduce_min_sync(0xFFu, smin[t]);
        emax = __reduce_max_sync(0xFFu, smax[t]);
        if (t == 0) {
            atomicMin(&g_min_enc, emin);
            atomicMax(&g_max_enc, emax);
        }
    }
}

// compare-exchange: u becomes max, v becomes min
#define SDP_CE(u, v) { float _hi = fmaxf(u, v), _lo = fminf(u, v); u = _hi; v = _lo; }

__device__ __forceinline__ void sdp_process_group(
    float4 va, float4 vb, float scale, float inv_scale,
    float4& oa, float4& ob)
{
    float xv[8]  = {va.x, va.y, va.z, va.w, vb.x, vb.y, vb.z, vb.w};
    float q[8];
    float mag[8];

    #pragma unroll
    for (int i = 0; i < 8; i++) {
        // Reciprocal-multiply fast path; can only flip round-half-to-even on
        // a near-.5 tie: detect and redo with exact IEEE division (rare).
        float y = xv[i] * inv_scale;
        float r = rintf(y);
        if (fabsf(fabsf(y - r) - 0.5f) < 1e-3f) {
            r = rintf(__fdiv_rn(xv[i], scale));
        }
        r = fminf(fmaxf(r, -128.0f), 127.0f);
        q[i]   = r;
        mag[i] = fabsf(r);   // integer-valued, 0..128
    }

    // 4th-largest of 8 via two sorted-4 runs + merge rank selection.
    float a0 = mag[0], a1 = mag[1], a2 = mag[2], a3 = mag[3];
    float b0 = mag[4], b1 = mag[5], b2 = mag[6], b3 = mag[7];
    SDP_CE(a0, a1); SDP_CE(a2, a3); SDP_CE(a0, a2); SDP_CE(a1, a3); SDP_CE(a1, a2);
    SDP_CE(b0, b1); SDP_CE(b2, b3); SDP_CE(b0, b2); SDP_CE(b1, b3); SDP_CE(b1, b2);
    float thr = fmaxf(fmaxf(a3, b3),
                      fmaxf(fminf(a0, b2), fmaxf(fminf(a1, b1), fminf(a2, b0))));

    #pragma unroll
    for (int i = 0; i < 8; i++) {
        const float tr16 = floorf(mag[i] * 0.0625f) * 16.0f;
        const float val  = (mag[i] >= thr) ? mag[i] : tr16;
        const float x_sdp = scale * copysignf(val, q[i]);
        xv[i] = xv[i] + (x_sdp - xv[i]);   // replicate reference rounding
    }

    oa = make_float4(xv[0], xv[1], xv[2], xv[3]);
    ob = make_float4(xv[4], xv[5], xv[6], xv[7]);
}

// One thread = two groups, pair layout (R13). REVERSED chunk order: first
// waves consume the L2-hot tail of x left by the minmax TMA pass.
__global__ void sdp_quant_kernel(const float4* __restrict__ x,
                                 float4* __restrict__ out) {
    const float r_min = dec_f(g_min_enc);
    const float r_max = dec_f(g_max_enc);
    const float scale = fmaxf(__fdiv_rn(r_max - r_min, 255.0f), 1e-8f);
    const float inv_scale = __frcp_rn(scale);

    const unsigned int cidx = gridDim.x - 1u - blockIdx.x;   // reverse order
    const size_t chunk = (size_t)cidx * 1024;   // float4 units
    const int t = threadIdx.x;
    const size_t i0 = chunk + 2 * t;          // first group (pair)
    const size_t i1 = chunk + 512 + 2 * t;    // second group (pair)

    float4 v0 = __ldcs(&x[i0]);
    float4 v1 = __ldcs(&x[i0 + 1]);
    float4 v2 = __ldcs(&x[i1]);
    float4 v3 = __ldcs(&x[i1 + 1]);

    float4 o0, o1, o2, o3;
    sdp_process_group(v0, v1, scale, inv_scale, o0, o1);
    sdp_process_group(v2, v3, scale, inv_scale, o2, o3);

    __stcs(&out[i0],     o0);
    __stcs(&out[i0 + 1], o1);
    __stcs(&out[i1],     o2);
    __stcs(&out[i1 + 1], o3);
}

extern "C" void kernel_launch(void* const* d_in, const int* in_sizes, int n_in,
                              void* d_out, int out_size) {
    const float* x = (const float*)d_in[0];
    float* out = (float*)d_out;
    const int n = in_sizes[0];          // 67,108,864 floats = 256 MB
    const int n4 = n >> 2;              // 16,777,216 float4

    const int threads = 256;

    const int mm_blocks = (int)((size_t)n * 4 / SDP_CHUNK_BYTES);  // 8192
    sdp_minmax_kernel<<<mm_blocks, threads>>>(x);

    const int q_blocks = n4 / 1024;     // 16384 chunks of 1024 float4
    sdp_quant_kernel<<<q_blocks, threads>>>((const float4*)x, (float4*)out);
}